// round 2
// baseline (speedup 1.0000x reference)
#include <cuda_runtime.h>
#include <cstdint>

#define NB   16
#define CIN  256
#define COUT 256
#define KS   5
#define SPK  128
#define TLEN 8192

#define ICH  16      // i-chunk in shared
#define OT   32      // o tile per block
#define TT   256     // t tile per block

// scratch (no cudaMalloc allowed)
__device__ float g_s[NB * CIN];
__device__ float g_demod[NB * COUT];
__device__ float g_wsqT[CIN * COUT];                       // [i][o]
__device__ float g_wm[(size_t)NB * KS * CIN * COUT];       // [b][k][i][o]

// ---------------------------------------------------------------------------
// s[b,i] = sum_j c_trg[b,j] * style_w[i,j] + style_b[i]
__global__ void style_kernel(const float* __restrict__ c_trg,
                             const float* __restrict__ style_w,
                             const float* __restrict__ style_b) {
    int b = blockIdx.x;
    int i = threadIdx.x;
    const float* c = c_trg + b * SPK;
    const float* w = style_w + i * SPK;
    float acc = 0.f;
#pragma unroll 8
    for (int j = 0; j < SPK; ++j) acc += c[j] * w[j];
    g_s[b * CIN + i] = acc + style_b[i];
}

// wsqT[i][o] = sum_k weight[o,i,k]^2
__global__ void wsq_kernel(const float* __restrict__ weight) {
    int i = blockIdx.x;
    int o = threadIdx.x;
    const float* wp = weight + ((size_t)o * CIN + i) * KS;
    float acc = 0.f;
#pragma unroll
    for (int k = 0; k < KS; ++k) acc += wp[k] * wp[k];
    g_wsqT[i * COUT + o] = acc;
}

// demod[b,o] = rsqrt( sum_i s[b,i]^2 * wsqT[i,o] + 1e-8 )
__global__ void demod_kernel() {
    int b = blockIdx.x;
    int o = threadIdx.x;
    const float* sp = g_s + b * CIN;
    float acc = 0.f;
#pragma unroll 4
    for (int i = 0; i < CIN; ++i) {
        float s = sp[i];
        acc += s * s * g_wsqT[i * COUT + o];
    }
    g_demod[b * COUT + o] = rsqrtf(acc + 1e-8f);
}

// g_wm[b][k][i][o] = weight[o,i,k] * s[b,i] * demod[b,o]
__global__ void wm_kernel(const float* __restrict__ weight) {
    int idx = blockIdx.x * blockDim.x + threadIdx.x;   // total NB*KS*CIN*COUT
    int o = idx & (COUT - 1);
    int i = (idx >> 8) & (CIN - 1);
    int kb = idx >> 16;          // b*KS + k
    int k = kb % KS;
    int b = kb / KS;
    float w = weight[((size_t)o * CIN + i) * KS + k];
    g_wm[idx] = w * g_s[b * CIN + i] * g_demod[b * COUT + o];
}

// ---------------------------------------------------------------------------
// Main conv: out[b,o,t] = leaky( sum_{i,k} Wm[b,o,i,k] * x_reflpad[b,i,t+k] )
__global__ __launch_bounds__(256)
void conv_kernel(const float* __restrict__ x, float* __restrict__ out) {
    __shared__ float Xs[ICH][TT + 4];
    __shared__ float Ws[KS][ICH][OT];

    const int b  = blockIdx.z;
    const int ob = blockIdx.y * OT;
    const int tb = blockIdx.x * TT;
    const int tid = threadIdx.x;
    const int og = tid >> 5;          // warp id = o group (0..7)
    const int to = tid & 31;          // t group within warp
    const int lt = to * 8;            // local t start

    float acc[4][8];
#pragma unroll
    for (int a = 0; a < 4; ++a)
#pragma unroll
        for (int j = 0; j < 8; ++j) acc[a][j] = 0.f;

    const float* xb = x + (size_t)b * CIN * TLEN;
    const float* wmb = g_wm + (size_t)b * KS * CIN * COUT;

    for (int ic = 0; ic < CIN; ic += ICH) {
        // --- fill Xs: rows = ICH channels, cols = TT+4 padded window ---
        for (int j = tid; j < ICH * (TT + 4); j += 256) {
            int i = j / (TT + 4);
            int u = j - i * (TT + 4);
            int t = tb + u - 2;                         // reflect pad (no edge repeat)
            t = (t < 0) ? -t : ((t >= TLEN) ? (2 * TLEN - 2 - t) : t);
            Xs[i][u] = xb[(size_t)(ic + i) * TLEN + t];
        }
        // --- fill Ws[k][i][o] from g_wm[b][k][ic+i][ob+o] (coalesced 128B rows) ---
        for (int j = tid; j < KS * ICH * OT; j += 256) {
            int k = j / (ICH * OT);
            int r = j - k * (ICH * OT);
            int i = r >> 5;
            int o = r & 31;
            Ws[k][i][o] = wmb[((size_t)k * CIN + ic + i) * COUT + ob + o];
        }
        __syncthreads();

#pragma unroll 2
        for (int i = 0; i < ICH; ++i) {
            float xr[12];
            *(float4*)&xr[0] = *(const float4*)&Xs[i][lt];
            *(float4*)&xr[4] = *(const float4*)&Xs[i][lt + 4];
            *(float4*)&xr[8] = *(const float4*)&Xs[i][lt + 8];
#pragma unroll
            for (int k = 0; k < KS; ++k) {
                float4 wv = *(const float4*)&Ws[k][i][og * 4];   // warp-broadcast
#pragma unroll
                for (int j = 0; j < 8; ++j) {
                    float xv = xr[j + k];
                    acc[0][j] = fmaf(wv.x, xv, acc[0][j]);
                    acc[1][j] = fmaf(wv.y, xv, acc[1][j]);
                    acc[2][j] = fmaf(wv.z, xv, acc[2][j]);
                    acc[3][j] = fmaf(wv.w, xv, acc[3][j]);
                }
            }
        }
        __syncthreads();
    }

    // --- epilogue: leaky relu + store ---
#pragma unroll
    for (int a = 0; a < 4; ++a) {
        int o = ob + og * 4 + a;
        float* op = out + ((size_t)b * COUT + o) * TLEN + tb + lt;
        float v[8];
#pragma unroll
        for (int j = 0; j < 8; ++j) {
            float z = acc[a][j];
            v[j] = (z > 0.f) ? z : 0.2f * z;
        }
        *(float4*)&op[0] = make_float4(v[0], v[1], v[2], v[3]);
        *(float4*)&op[4] = make_float4(v[4], v[5], v[6], v[7]);
    }
}

// ---------------------------------------------------------------------------
extern "C" void kernel_launch(void* const* d_in, const int* in_sizes, int n_in,
                              void* d_out, int out_size) {
    const float* x       = (const float*)d_in[0];   // [16,256,8192]
    const float* c_trg   = (const float*)d_in[1];   // [16,128]
    const float* style_w = (const float*)d_in[2];   // [256,128]
    const float* style_b = (const float*)d_in[3];   // [256]
    const float* weight  = (const float*)d_in[4];   // [1,256,256,5]
    float* out = (float*)d_out;

    style_kernel<<<NB, CIN>>>(c_trg, style_w, style_b);
    wsq_kernel<<<CIN, COUT>>>(weight);
    demod_kernel<<<NB, COUT>>>();
    {
        int total = NB * KS * CIN * COUT;             // 5,242,880
        wm_kernel<<<total / 256, 256>>>(weight);
    }
    {
        dim3 grid(TLEN / TT, COUT / OT, NB);          // (32, 8, 16)
        conv_kernel<<<grid, 256>>>(x, out);
    }
    // passthrough second output: c_trg appended after conv output
    size_t conv_elems = (size_t)NB * COUT * TLEN;     // 33,554,432
    if ((size_t)out_size > conv_elems) {
        cudaMemcpyAsync(out + conv_elems, c_trg,
                        (out_size - conv_elems) * sizeof(float),
                        cudaMemcpyDeviceToDevice);
    }
}

// round 3
// speedup vs baseline: 1.1294x; 1.1294x over previous
#include <cuda_runtime.h>
#include <cstdint>

#define NB   16
#define CIN  256
#define COUT 256
#define KS   5
#define SPK  128
#define TLEN 8192

#define ICH  16      // i-chunk in shared
#define OT   32      // o tile per block
#define TT   256     // t tile per block

// scratch (no cudaMalloc allowed)
__device__ float g_s[NB * CIN];
__device__ float g_demod[NB * COUT];
__device__ float g_wsqT[CIN * COUT];                       // [i][o]
__device__ float g_wm[(size_t)NB * KS * CIN * COUT];       // [b][k][i][o]

// ---------------------------------------------------------------------------
// packed f32x2 helpers (sm_103a FFMA2 path — ptxas never emits this itself)
__device__ __forceinline__ unsigned long long dup2(float x) {
    unsigned long long r;
    unsigned xi = __float_as_uint(x);
    asm("mov.b64 %0, {%1, %1};" : "=l"(r) : "r"(xi));
    return r;
}
__device__ __forceinline__ void fma2(unsigned long long& acc,
                                     unsigned long long w,
                                     unsigned long long x) {
    asm("fma.rn.f32x2 %0, %1, %2, %0;" : "+l"(acc) : "l"(w), "l"(x));
}
__device__ __forceinline__ void unpack2(unsigned long long v, float& lo, float& hi) {
    unsigned a, b;
    asm("mov.b64 {%0, %1}, %2;" : "=r"(a), "=r"(b) : "l"(v));
    lo = __uint_as_float(a);
    hi = __uint_as_float(b);
}

// ---------------------------------------------------------------------------
// s[b,i] = sum_j c_trg[b,j] * style_w[i,j] + style_b[i]
__global__ void style_kernel(const float* __restrict__ c_trg,
                             const float* __restrict__ style_w,
                             const float* __restrict__ style_b) {
    int b = blockIdx.x;
    int i = threadIdx.x;
    const float* c = c_trg + b * SPK;
    const float* w = style_w + i * SPK;
    float acc = 0.f;
#pragma unroll 8
    for (int j = 0; j < SPK; ++j) acc += c[j] * w[j];
    g_s[b * CIN + i] = acc + style_b[i];
}

// wsqT[i][o] = sum_k weight[o,i,k]^2
__global__ void wsq_kernel(const float* __restrict__ weight) {
    int i = blockIdx.x;
    int o = threadIdx.x;
    const float* wp = weight + ((size_t)o * CIN + i) * KS;
    float acc = 0.f;
#pragma unroll
    for (int k = 0; k < KS; ++k) acc += wp[k] * wp[k];
    g_wsqT[i * COUT + o] = acc;
}

// demod[b,o] = rsqrt( sum_i s[b,i]^2 * wsqT[i,o] + 1e-8 )
__global__ void demod_kernel() {
    int b = blockIdx.x;
    int o = threadIdx.x;
    const float* sp = g_s + b * CIN;
    float acc = 0.f;
#pragma unroll 4
    for (int i = 0; i < CIN; ++i) {
        float s = sp[i];
        acc += s * s * g_wsqT[i * COUT + o];
    }
    g_demod[b * COUT + o] = rsqrtf(acc + 1e-8f);
}

// g_wm[b][k][i][o] = weight[o,i,k] * s[b,i] * demod[b,o]
__global__ void wm_kernel(const float* __restrict__ weight) {
    int idx = blockIdx.x * blockDim.x + threadIdx.x;   // total NB*KS*CIN*COUT
    int o = idx & (COUT - 1);
    int i = (idx >> 8) & (CIN - 1);
    int kb = idx >> 16;          // b*KS + k
    int k = kb % KS;
    int b = kb / KS;
    float w = weight[((size_t)o * CIN + i) * KS + k];
    g_wm[idx] = w * g_s[b * CIN + i] * g_demod[b * COUT + o];
}

// ---------------------------------------------------------------------------
// Main conv: out[b,o,t] = leaky( sum_{i,k} Wm[b,o,i,k] * x_reflpad[b,i,t+k] )
// Inner loop on packed f32x2 (pair across adjacent output channels).
__global__ __launch_bounds__(256)
void conv_kernel(const float* __restrict__ x, float* __restrict__ out) {
    __shared__ __align__(16) float Xs[ICH][TT + 4];
    __shared__ __align__(16) float Ws[KS][ICH][OT];

    const int b  = blockIdx.z;
    const int ob = blockIdx.y * OT;
    const int tb = blockIdx.x * TT;
    const int tid = threadIdx.x;
    const int og = tid >> 5;          // warp id = o group (0..7), 4 o's each
    const int to = tid & 31;          // t group within warp
    const int lt = to * 8;            // local t start

    // acc2[p][j]: p = o-pair within og's 4 outputs, halves = (o, o+1); j = t
    unsigned long long acc2[2][8];
#pragma unroll
    for (int p = 0; p < 2; ++p)
#pragma unroll
        for (int j = 0; j < 8; ++j) acc2[p][j] = 0ull;

    const float* xb = x + (size_t)b * CIN * TLEN;
    const float* wmb = g_wm + (size_t)b * KS * CIN * COUT;

    for (int ic = 0; ic < CIN; ic += ICH) {
        // --- fill Xs: rows = ICH channels, cols = TT+4 padded window ---
        for (int j = tid; j < ICH * (TT + 4); j += 256) {
            int i = j / (TT + 4);
            int u = j - i * (TT + 4);
            int t = tb + u - 2;                         // reflect pad (no edge repeat)
            t = (t < 0) ? -t : ((t >= TLEN) ? (2 * TLEN - 2 - t) : t);
            Xs[i][u] = xb[(size_t)(ic + i) * TLEN + t];
        }
        // --- fill Ws[k][i][o] from g_wm[b][k][ic+i][ob+o] (coalesced 128B rows) ---
        for (int j = tid; j < KS * ICH * OT; j += 256) {
            int k = j / (ICH * OT);
            int r = j - k * (ICH * OT);
            int i = r >> 5;
            int o = r & 31;
            Ws[k][i][o] = wmb[((size_t)k * CIN + ic + i) * COUT + ob + o];
        }
        __syncthreads();

#pragma unroll 2
        for (int i = 0; i < ICH; ++i) {
            float xr[12];
            *(float4*)&xr[0] = *(const float4*)&Xs[i][lt];
            *(float4*)&xr[4] = *(const float4*)&Xs[i][lt + 4];
            *(float4*)&xr[8] = *(const float4*)&Xs[i][lt + 8];
            unsigned long long xd[12];
#pragma unroll
            for (int m = 0; m < 12; ++m) xd[m] = dup2(xr[m]);   // alu pipe, hides under fma
#pragma unroll
            for (int k = 0; k < KS; ++k) {
                // adjacent o's are adjacent floats -> aligned LDS.64 gives the pair
                unsigned long long w0 = *(const unsigned long long*)&Ws[k][i][og * 4];
                unsigned long long w1 = *(const unsigned long long*)&Ws[k][i][og * 4 + 2];
#pragma unroll
                for (int j = 0; j < 8; ++j) {
                    fma2(acc2[0][j], w0, xd[j + k]);
                    fma2(acc2[1][j], w1, xd[j + k]);
                }
            }
        }
        __syncthreads();
    }

    // --- epilogue: unpack pairs, leaky relu, store ---
#pragma unroll
    for (int p = 0; p < 2; ++p) {
        float lo[8], hi[8];
#pragma unroll
        for (int j = 0; j < 8; ++j) unpack2(acc2[p][j], lo[j], hi[j]);

        int o0 = ob + og * 4 + 2 * p;
        float* op0 = out + ((size_t)b * COUT + o0) * TLEN + tb + lt;
        float* op1 = op0 + TLEN;
        float v0[8], v1[8];
#pragma unroll
        for (int j = 0; j < 8; ++j) {
            v0[j] = (lo[j] > 0.f) ? lo[j] : 0.2f * lo[j];
            v1[j] = (hi[j] > 0.f) ? hi[j] : 0.2f * hi[j];
        }
        *(float4*)&op0[0] = make_float4(v0[0], v0[1], v0[2], v0[3]);
        *(float4*)&op0[4] = make_float4(v0[4], v0[5], v0[6], v0[7]);
        *(float4*)&op1[0] = make_float4(v1[0], v1[1], v1[2], v1[3]);
        *(float4*)&op1[4] = make_float4(v1[4], v1[5], v1[6], v1[7]);
    }
}

// ---------------------------------------------------------------------------
extern "C" void kernel_launch(void* const* d_in, const int* in_sizes, int n_in,
                              void* d_out, int out_size) {
    const float* x       = (const float*)d_in[0];   // [16,256,8192]
    const float* c_trg   = (const float*)d_in[1];   // [16,128]
    const float* style_w = (const float*)d_in[2];   // [256,128]
    const float* style_b = (const float*)d_in[3];   // [256]
    const float* weight  = (const float*)d_in[4];   // [1,256,256,5]
    float* out = (float*)d_out;

    style_kernel<<<NB, CIN>>>(c_trg, style_w, style_b);
    wsq_kernel<<<CIN, COUT>>>(weight);
    demod_kernel<<<NB, COUT>>>();
    {
        int total = NB * KS * CIN * COUT;             // 5,242,880
        wm_kernel<<<total / 256, 256>>>(weight);
    }
    {
        dim3 grid(TLEN / TT, COUT / OT, NB);          // (32, 8, 16)
        conv_kernel<<<grid, 256>>>(x, out);
    }
    // passthrough second output: c_trg appended after conv output
    size_t conv_elems = (size_t)NB * COUT * TLEN;     // 33,554,432
    if ((size_t)out_size > conv_elems) {
        cudaMemcpyAsync(out + conv_elems, c_trg,
                        (out_size - conv_elems) * sizeof(float),
                        cudaMemcpyDeviceToDevice);
    }
}

// round 4
// speedup vs baseline: 1.9480x; 1.7248x over previous
#include <cuda_runtime.h>
#include <cuda_bf16.h>
#include <cstdint>

#define NB   16
#define CIN  256
#define COUT 256
#define KS   5
#define SPK  128
#define TLEN 8192

#define OTI  64      // o tile per block
#define TTI  256     // t tile per block
#define ICH  32      // i chunk
#define XR   36      // padded row length (i) in bf16 elems
#define XT   260     // xs rows (t range: tile + 4 pad)

// scratch (no cudaMalloc allowed)
__device__ float g_s[NB * CIN];
__device__ float g_demod[NB * COUT];
__device__ float g_wsqT[CIN * COUT];                                   // [i][o]
__device__ __nv_bfloat16 g_wmh[(size_t)NB * KS * COUT * CIN];          // [b][k][o][i]
__device__ __nv_bfloat16 g_wml[(size_t)NB * KS * COUT * CIN];

// ---------------------------------------------------------------------------
__global__ void style_kernel(const float* __restrict__ c_trg,
                             const float* __restrict__ style_w,
                             const float* __restrict__ style_b) {
    int b = blockIdx.x;
    int i = threadIdx.x;
    const float* c = c_trg + b * SPK;
    const float* w = style_w + i * SPK;
    float acc = 0.f;
#pragma unroll 8
    for (int j = 0; j < SPK; ++j) acc += c[j] * w[j];
    g_s[b * CIN + i] = acc + style_b[i];
}

__global__ void wsq_kernel(const float* __restrict__ weight) {
    int i = blockIdx.x;
    int o = threadIdx.x;
    const float* wp = weight + ((size_t)o * CIN + i) * KS;
    float acc = 0.f;
#pragma unroll
    for (int k = 0; k < KS; ++k) acc += wp[k] * wp[k];
    g_wsqT[i * COUT + o] = acc;
}

__global__ void demod_kernel() {
    int b = blockIdx.x;
    int o = threadIdx.x;
    const float* sp = g_s + b * CIN;
    float acc = 0.f;
#pragma unroll 4
    for (int i = 0; i < CIN; ++i) {
        float s = sp[i];
        acc += s * s * g_wsqT[i * COUT + o];
    }
    g_demod[b * COUT + o] = rsqrtf(acc + 1e-8f);
}

// g_wmh/g_wml[b][k][o][i] = bf16 hi/lo split of weight[o,i,k]*s[b,i]*demod[b,o]
__global__ void wm_kernel(const float* __restrict__ weight) {
    int idx = blockIdx.x * blockDim.x + threadIdx.x;   // NB*KS*COUT*CIN
    int i = idx & (CIN - 1);
    int o = (idx >> 8) & (COUT - 1);
    int kb = idx >> 16;          // b*KS + k
    int k = kb % KS;
    int b = kb / KS;
    float wv = weight[((size_t)o * CIN + i) * KS + k]
             * g_s[b * CIN + i] * g_demod[b * COUT + o];
    __nv_bfloat16 h = __float2bfloat16(wv);
    g_wmh[idx] = h;
    g_wml[idx] = __float2bfloat16(wv - __bfloat162float(h));
}

// ---------------------------------------------------------------------------
__device__ __forceinline__ void mma16816(float* d, const unsigned* a,
                                         unsigned b0, unsigned b1) {
    asm volatile(
        "mma.sync.aligned.m16n8k16.row.col.f32.bf16.bf16.f32 "
        "{%0,%1,%2,%3}, {%4,%5,%6,%7}, {%8,%9}, {%0,%1,%2,%3};"
        : "+f"(d[0]), "+f"(d[1]), "+f"(d[2]), "+f"(d[3])
        : "r"(a[0]), "r"(a[1]), "r"(a[2]), "r"(a[3]), "r"(b0), "r"(b1));
}

__device__ __forceinline__ unsigned lds32(const __nv_bfloat16* p) {
    return *(const unsigned*)p;
}

// Main conv: out[b,o,t] = leaky( sum_{i,k} Wm[b,o,i,k] * x_reflpad[b,i,t+k] )
// bf16 tensor cores, 3-term hi/lo split.
__global__ __launch_bounds__(256, 2)
void conv_kernel(const float* __restrict__ x, float* __restrict__ out) {
    extern __shared__ __align__(16) char smem_raw[];
    __nv_bfloat16* xs_h = (__nv_bfloat16*)smem_raw;                // [XT][XR]
    __nv_bfloat16* xs_l = xs_h + XT * XR;
    __nv_bfloat16* ws_h = xs_l + XT * XR;                          // [KS][OTI][XR]
    __nv_bfloat16* ws_l = ws_h + KS * OTI * XR;

    const int b  = blockIdx.z;
    const int ob = blockIdx.y * OTI;
    const int tb = blockIdx.x * TTI;
    const int tid = threadIdx.x;
    const int wid = tid >> 5;
    const int lane = tid & 31;
    const int wo = wid & 1;           // o warp (2): 32 o each
    const int wt = wid >> 1;          // t warp (4): 64 t each
    const int lq = lane >> 2;         // lane / 4
    const int lr = lane & 3;          // lane % 4

    float acc[2][8][4];
#pragma unroll
    for (int mt = 0; mt < 2; ++mt)
#pragma unroll
        for (int nt = 0; nt < 8; ++nt)
#pragma unroll
            for (int e = 0; e < 4; ++e) acc[mt][nt][e] = 0.f;

    const float* xb = x + (size_t)b * CIN * TLEN;
    const __nv_bfloat16* wmhb = g_wmh + (size_t)b * KS * COUT * CIN;
    const __nv_bfloat16* wmlb = g_wml + (size_t)b * KS * COUT * CIN;

    for (int ic = 0; ic < CIN; ic += ICH) {
        __syncthreads();
        // --- xs fill: transpose + reflect pad + hi/lo split ---
        for (int u = tid; u < ICH * XT; u += 256) {
            int i  = u / XT;
            int tl = u - i * XT;
            int t  = tb + tl - 2;
            t = (t < 0) ? -t : ((t >= TLEN) ? (2 * TLEN - 2 - t) : t);
            float v = xb[(size_t)(ic + i) * TLEN + t];
            __nv_bfloat16 h = __float2bfloat16(v);
            xs_h[tl * XR + i] = h;
            xs_l[tl * XR + i] = __float2bfloat16(v - __bfloat162float(h));
        }
        // --- ws fill: [k][o][i] from g_wm[b][k][ob+o][ic+i] ---
        for (int u = tid; u < KS * OTI * ICH; u += 256) {
            int k = u >> 11;                  // / (64*32)
            int r = u & 2047;
            int o = r >> 5;
            int i = r & 31;
            size_t gi = ((size_t)k * COUT + ob + o) * CIN + ic + i;
            ws_h[(k * OTI + o) * XR + i] = wmhb[gi];
            ws_l[(k * OTI + o) * XR + i] = wmlb[gi];
        }
        __syncthreads();

        for (int tap = 0; tap < KS; ++tap) {
#pragma unroll
            for (int k16 = 0; k16 < ICH; k16 += 16) {
                // A fragments (W): rows o, cols i
                unsigned ah[2][4], al[2][4];
#pragma unroll
                for (int mt = 0; mt < 2; ++mt) {
                    int row = tap * OTI + wo * 32 + mt * 16 + lq;
                    int col = k16 + lr * 2;
                    const __nv_bfloat16* ph = ws_h + row * XR + col;
                    const __nv_bfloat16* pl = ws_l + row * XR + col;
                    ah[mt][0] = lds32(ph);
                    ah[mt][1] = lds32(ph + 8 * XR);
                    ah[mt][2] = lds32(ph + 8);
                    ah[mt][3] = lds32(ph + 8 * XR + 8);
                    al[mt][0] = lds32(pl);
                    al[mt][1] = lds32(pl + 8 * XR);
                    al[mt][2] = lds32(pl + 8);
                    al[mt][3] = lds32(pl + 8 * XR + 8);
                }
#pragma unroll
                for (int nt = 0; nt < 8; ++nt) {
                    int trow = wt * 64 + nt * 8 + lq + tap;   // tap shift = row offset
                    int col  = k16 + lr * 2;
                    const __nv_bfloat16* ph = xs_h + trow * XR + col;
                    const __nv_bfloat16* pl = xs_l + trow * XR + col;
                    unsigned bh0 = lds32(ph), bh1 = lds32(ph + 8);
                    unsigned bl0 = lds32(pl), bl1 = lds32(pl + 8);
#pragma unroll
                    for (int mt = 0; mt < 2; ++mt) {
                        mma16816(acc[mt][nt], ah[mt], bh0, bh1);  // hi*hi
                        mma16816(acc[mt][nt], ah[mt], bl0, bl1);  // hi*lo
                        mma16816(acc[mt][nt], al[mt], bh0, bh1);  // lo*hi
                    }
                }
            }
        }
    }

    // --- epilogue: leaky relu + store ---
    // C frag: c0,c1 -> row m=lq,  cols n=lr*2,lr*2+1 ; c2,c3 -> row m=lq+8
#pragma unroll
    for (int mt = 0; mt < 2; ++mt) {
#pragma unroll
        for (int nt = 0; nt < 8; ++nt) {
            int o0 = ob + wo * 32 + mt * 16 + lq;
            int t0 = tb + wt * 64 + nt * 8 + lr * 2;
            float z0 = acc[mt][nt][0], z1 = acc[mt][nt][1];
            float z2 = acc[mt][nt][2], z3 = acc[mt][nt][3];
            z0 = (z0 > 0.f) ? z0 : 0.2f * z0;
            z1 = (z1 > 0.f) ? z1 : 0.2f * z1;
            z2 = (z2 > 0.f) ? z2 : 0.2f * z2;
            z3 = (z3 > 0.f) ? z3 : 0.2f * z3;
            float* p0 = out + ((size_t)b * COUT + o0) * TLEN + t0;
            *(float2*)p0 = make_float2(z0, z1);
            *(float2*)(p0 + 8 * TLEN) = make_float2(z2, z3);
        }
    }
}

// ---------------------------------------------------------------------------
extern "C" void kernel_launch(void* const* d_in, const int* in_sizes, int n_in,
                              void* d_out, int out_size) {
    const float* x       = (const float*)d_in[0];   // [16,256,8192]
    const float* c_trg   = (const float*)d_in[1];   // [16,128]
    const float* style_w = (const float*)d_in[2];   // [256,128]
    const float* style_b = (const float*)d_in[3];   // [256]
    const float* weight  = (const float*)d_in[4];   // [1,256,256,5]
    float* out = (float*)d_out;

    style_kernel<<<NB, CIN>>>(c_trg, style_w, style_b);
    wsq_kernel<<<CIN, COUT>>>(weight);
    demod_kernel<<<NB, COUT>>>();
    {
        int total = NB * KS * CIN * COUT;             // 5,242,880
        wm_kernel<<<total / 256, 256>>>(weight);
    }
    {
        static bool attr_done = false;
        int smem_bytes = (2 * XT * XR + 2 * KS * OTI * XR) * (int)sizeof(__nv_bfloat16);
        if (!attr_done) {
            cudaFuncSetAttribute(conv_kernel,
                                 cudaFuncAttributeMaxDynamicSharedMemorySize,
                                 smem_bytes);
            attr_done = true;
        }
        dim3 grid(TLEN / TTI, COUT / OTI, NB);        // (32, 4, 16)
        conv_kernel<<<grid, 256, smem_bytes>>>(x, out);
    }
    // passthrough second output: c_trg appended after conv output
    size_t conv_elems = (size_t)NB * COUT * TLEN;     // 33,554,432
    if ((size_t)out_size > conv_elems) {
        cudaMemcpyAsync(out + conv_elems, c_trg,
                        (out_size - conv_elems) * sizeof(float),
                        cudaMemcpyDeviceToDevice);
    }
}

// round 8
// speedup vs baseline: 2.1939x; 1.1262x over previous
#include <cuda_runtime.h>
#include <cuda_bf16.h>
#include <cstdint>

#define NB   16
#define CIN  256
#define COUT 256
#define KS   5
#define SPK  128
#define TLEN 8192

#define OTI  64      // o tile per block
#define TTI  256     // t tile per block
#define ICH  32      // i chunk
#define XR   40      // padded row pitch (80B -> 16B-aligned quarters)
#define XT   260     // xs rows (t range: tile + 4 pad)
#define NCH  8       // CIN / ICH

#define XS_ST (XT * XR)          // 10400 elems per stage
#define WS_ST (KS * OTI * XR)    // 12800 elems per stage
#define SMEM_BYTES ((4 * XS_ST + 4 * WS_ST) * 2)   // 185600

// scratch (no cudaMalloc allowed)
__device__ float g_s[NB * CIN];
__device__ float g_demod[NB * COUT];
__device__ float g_wsqT[CIN * COUT];                                   // [i][o]
__device__ __nv_bfloat16 g_wmh[(size_t)NB * KS * COUT * CIN];          // [b][k][o][i]
__device__ __nv_bfloat16 g_wml[(size_t)NB * KS * COUT * CIN];

// ---------------------------------------------------------------------------
__global__ void style_kernel(const float* __restrict__ c_trg,
                             const float* __restrict__ style_w,
                             const float* __restrict__ style_b) {
    int b = blockIdx.x;
    int i = threadIdx.x;
    const float* c = c_trg + b * SPK;
    const float* w = style_w + i * SPK;
    float acc = 0.f;
#pragma unroll 8
    for (int j = 0; j < SPK; ++j) acc += c[j] * w[j];
    g_s[b * CIN + i] = acc + style_b[i];
}

__global__ void wsq_kernel(const float* __restrict__ weight) {
    int i = blockIdx.x;
    int o = threadIdx.x;
    const float* wp = weight + ((size_t)o * CIN + i) * KS;
    float acc = 0.f;
#pragma unroll
    for (int k = 0; k < KS; ++k) acc += wp[k] * wp[k];
    g_wsqT[i * COUT + o] = acc;
}

__global__ void demod_kernel() {
    int b = blockIdx.x;
    int o = threadIdx.x;
    const float* sp = g_s + b * CIN;
    float acc = 0.f;
#pragma unroll 4
    for (int i = 0; i < CIN; ++i) {
        float s = sp[i];
        acc += s * s * g_wsqT[i * COUT + o];
    }
    g_demod[b * COUT + o] = rsqrtf(acc + 1e-8f);
}

// g_wmh/g_wml[b][k][o][i] = bf16 hi/lo split of weight[o,i,k]*s[b,i]*demod[b,o]
__global__ void wm_kernel(const float* __restrict__ weight) {
    int idx = blockIdx.x * blockDim.x + threadIdx.x;   // NB*KS*COUT*CIN
    int i = idx & (CIN - 1);
    int o = (idx >> 8) & (COUT - 1);
    int kb = idx >> 16;
    int k = kb % KS;
    int b = kb / KS;
    float wv = weight[((size_t)o * CIN + i) * KS + k]
             * g_s[b * CIN + i] * g_demod[b * COUT + o];
    __nv_bfloat16 h = __float2bfloat16(wv);
    g_wmh[idx] = h;
    g_wml[idx] = __float2bfloat16(wv - __bfloat162float(h));
}

// ---------------------------------------------------------------------------
__device__ __forceinline__ void mma16816(float* d, const unsigned* a,
                                         unsigned b0, unsigned b1) {
    asm volatile(
        "mma.sync.aligned.m16n8k16.row.col.f32.bf16.bf16.f32 "
        "{%0,%1,%2,%3}, {%4,%5,%6,%7}, {%8,%9}, {%0,%1,%2,%3};"
        : "+f"(d[0]), "+f"(d[1]), "+f"(d[2]), "+f"(d[3])
        : "r"(a[0]), "r"(a[1]), "r"(a[2]), "r"(a[3]), "r"(b0), "r"(b1));
}
__device__ __forceinline__ unsigned lds32(const __nv_bfloat16* p) {
    return *(const unsigned*)p;
}
__device__ __forceinline__ uint32_t smem_u32(const void* p) {
    uint32_t a;
    asm("{ .reg .u64 t; cvta.to.shared.u64 t, %1; cvt.u32.u64 %0, t; }"
        : "=r"(a) : "l"(p));
    return a;
}
__device__ __forceinline__ void cp16(uint32_t dst, const void* src) {
    asm volatile("cp.async.cg.shared.global [%0], [%1], 16;"
                 :: "r"(dst), "l"(src));
}
#define CP_COMMIT() asm volatile("cp.async.commit_group;" ::: "memory")
#define CP_WAIT0()  asm volatile("cp.async.wait_group 0;" ::: "memory")

__device__ __forceinline__ float ldg_f32(const float* p) {
    float v;
    asm volatile("ld.global.nc.f32 %0, [%1];" : "=f"(v) : "l"(p));
    return v;
}

// ---------------------------------------------------------------------------
// Main conv: out[b,o,t] = leaky( sum_{i,k} Wm[b,o,i,k] * x_reflpad[b,i,t+k] )
// bf16 mma.sync, 3-term hi/lo split, double-buffered smem + cp.async weights.
__global__ __launch_bounds__(256, 1)
void conv_kernel(const float* __restrict__ x, float* __restrict__ out) {
    extern __shared__ __align__(16) __nv_bfloat16 sm[];
    __nv_bfloat16* xs_h = sm;                        // [2][XS_ST]
    __nv_bfloat16* xs_l = sm + 2 * XS_ST;
    __nv_bfloat16* ws_h = sm + 4 * XS_ST;            // [2][WS_ST]
    __nv_bfloat16* ws_l = sm + 4 * XS_ST + 2 * WS_ST;
    const uint32_t wsh_a = smem_u32(ws_h);
    const uint32_t wsl_a = smem_u32(ws_l);

    const int b  = blockIdx.z;
    const int ob = blockIdx.y * OTI;
    const int tb = blockIdx.x * TTI;
    const int tid = threadIdx.x;
    const int wid = tid >> 5;
    const int lane = tid & 31;
    const int wo = wid & 1;           // o warp (2): 32 o each
    const int wt = wid >> 1;          // t warp (4): 64 t each
    const int lq = lane >> 2;
    const int lr = lane & 3;

    float acc[2][8][4];
#pragma unroll
    for (int mt = 0; mt < 2; ++mt)
#pragma unroll
        for (int nt = 0; nt < 8; ++nt)
#pragma unroll
            for (int e = 0; e < 4; ++e) acc[mt][nt][e] = 0.f;

    const float* xb = x + (size_t)b * CIN * TLEN;
    const __nv_bfloat16* wmhb = g_wmh + (size_t)b * KS * COUT * CIN;
    const __nv_bfloat16* wmlb = g_wml + (size_t)b * KS * COUT * CIN;

    float xr[33];

    // ---- prefetch Ws for chunk at ic into stage st (pure cp.async, 16B chunks) ----
    // Each row holds 64B of data (32 bf16) in an 80B pitch; 4 chunks of 16B.
    auto prefetch_w = [&](int ic, int st) {
#pragma unroll
        for (int m = 0; m < 10; ++m) {
            int v = tid + 256 * m;                  // < 2560 = 2 arrays * 320 rows * 4
            int arr = v / 1280;
            int r   = v - arr * 1280;
            int row = r >> 2;                        // k*OTI + o  (0..319)
            int c4  = r & 3;                         // 16B chunk within row
            int k = row >> 6;
            int o = row & 63;
            const __nv_bfloat16* src =
                (arr ? wmlb : wmhb) + ((size_t)(k * COUT + ob + o) * CIN + ic) + c4 * 8;
            uint32_t dst = (arr ? wsl_a : wsh_a) +
                           (uint32_t)(st * WS_ST + row * XR) * 2 + c4 * 16;
            cp16(dst, src);
        }
        CP_COMMIT();
    };
    // ---- issue x LDGs for chunk into regs (latency hidden under MMAs) ----
    auto load_x = [&](int ic) {
#pragma unroll
        for (int j = 0; j < 33; ++j) {
            int u = tid + 256 * j;
            if (u < ICH * XT) {
                int i  = u / XT;
                int tl = u - i * XT;
                int t  = tb + tl - 2;
                t = (t < 0) ? -t : ((t >= TLEN) ? (2 * TLEN - 2 - t) : t);
                xr[j] = ldg_f32(xb + (size_t)(ic + i) * TLEN + t);
            }
        }
    };
    // ---- convert + store x regs into stage st ----
    auto store_x = [&](int st) {
#pragma unroll
        for (int j = 0; j < 33; ++j) {
            int u = tid + 256 * j;
            if (u < ICH * XT) {
                int i  = u / XT;
                int tl = u - i * XT;
                float v = xr[j];
                __nv_bfloat16 h = __float2bfloat16(v);
                xs_h[st * XS_ST + tl * XR + i] = h;
                xs_l[st * XS_ST + tl * XR + i] =
                    __float2bfloat16(v - __bfloat162float(h));
            }
        }
    };

    // ---- prologue: fill stage 0 ----
    prefetch_w(0, 0);
    load_x(0);
    store_x(0);
    CP_WAIT0();
    __syncthreads();

    for (int c = 0; c < NCH; ++c) {
        const int st = c & 1;
        const int nst = st ^ 1;
        if (c + 1 < NCH) {
            prefetch_w((c + 1) * ICH, nst);
            load_x((c + 1) * ICH);
        }

        // ---- MMA over stage st ----
        const __nv_bfloat16* wsh = ws_h + st * WS_ST;
        const __nv_bfloat16* wsl = ws_l + st * WS_ST;
        const __nv_bfloat16* xhh = xs_h + st * XS_ST;
        const __nv_bfloat16* xll = xs_l + st * XS_ST;

        for (int tap = 0; tap < KS; ++tap) {
#pragma unroll
            for (int k16 = 0; k16 < ICH; k16 += 16) {
                unsigned ah[2][4], al[2][4];
#pragma unroll
                for (int mt = 0; mt < 2; ++mt) {
                    int row = tap * OTI + wo * 32 + mt * 16 + lq;
                    int col = k16 + lr * 2;
                    const __nv_bfloat16* ph = wsh + row * XR + col;
                    const __nv_bfloat16* pl = wsl + row * XR + col;
                    ah[mt][0] = lds32(ph);
                    ah[mt][1] = lds32(ph + 8 * XR);
                    ah[mt][2] = lds32(ph + 8);
                    ah[mt][3] = lds32(ph + 8 * XR + 8);
                    al[mt][0] = lds32(pl);
                    al[mt][1] = lds32(pl + 8 * XR);
                    al[mt][2] = lds32(pl + 8);
                    al[mt][3] = lds32(pl + 8 * XR + 8);
                }
#pragma unroll
                for (int nt = 0; nt < 8; ++nt) {
                    int trow = wt * 64 + nt * 8 + lq + tap;
                    int col  = k16 + lr * 2;
                    const __nv_bfloat16* ph = xhh + trow * XR + col;
                    const __nv_bfloat16* pl = xll + trow * XR + col;
                    unsigned bh0 = lds32(ph), bh1 = lds32(ph + 8);
                    unsigned bl0 = lds32(pl), bl1 = lds32(pl + 8);
#pragma unroll
                    for (int mt = 0; mt < 2; ++mt) {
                        mma16816(acc[mt][nt], ah[mt], bh0, bh1);  // hi*hi
                        mma16816(acc[mt][nt], ah[mt], bl0, bl1);  // hi*lo
                        mma16816(acc[mt][nt], al[mt], bh0, bh1);  // lo*hi
                    }
                }
            }
        }

        if (c + 1 < NCH) {
            store_x(nst);
            CP_WAIT0();
        }
        __syncthreads();
    }

    // ---- epilogue: leaky relu + store ----
#pragma unroll
    for (int mt = 0; mt < 2; ++mt) {
#pragma unroll
        for (int nt = 0; nt < 8; ++nt) {
            int o0 = ob + wo * 32 + mt * 16 + lq;
            int t0 = tb + wt * 64 + nt * 8 + lr * 2;
            float z0 = acc[mt][nt][0], z1 = acc[mt][nt][1];
            float z2 = acc[mt][nt][2], z3 = acc[mt][nt][3];
            z0 = (z0 > 0.f) ? z0 : 0.2f * z0;
            z1 = (z1 > 0.f) ? z1 : 0.2f * z1;
            z2 = (z2 > 0.f) ? z2 : 0.2f * z2;
            z3 = (z3 > 0.f) ? z3 : 0.2f * z3;
            float* p0 = out + ((size_t)b * COUT + o0) * TLEN + t0;
            *(float2*)p0 = make_float2(z0, z1);
            *(float2*)(p0 + 8 * TLEN) = make_float2(z2, z3);
        }
    }
}

// ---------------------------------------------------------------------------
extern "C" void kernel_launch(void* const* d_in, const int* in_sizes, int n_in,
                              void* d_out, int out_size) {
    const float* x       = (const float*)d_in[0];   // [16,256,8192]
    const float* c_trg   = (const float*)d_in[1];   // [16,128]
    const float* style_w = (const float*)d_in[2];   // [256,128]
    const float* style_b = (const float*)d_in[3];   // [256]
    const float* weight  = (const float*)d_in[4];   // [1,256,256,5]
    float* out = (float*)d_out;

    style_kernel<<<NB, CIN>>>(c_trg, style_w, style_b);
    wsq_kernel<<<CIN, COUT>>>(weight);
    demod_kernel<<<NB, COUT>>>();
    wm_kernel<<<(NB * KS * CIN * COUT) / 256, 256>>>(weight);

    static bool attr_done = false;
    if (!attr_done) {
        cudaFuncSetAttribute(conv_kernel,
                             cudaFuncAttributeMaxDynamicSharedMemorySize,
                             SMEM_BYTES);
        attr_done = true;
    }
    dim3 grid(TLEN / TTI, COUT / OTI, NB);        // (32, 4, 16)
    conv_kernel<<<grid, 256, SMEM_BYTES>>>(x, out);

    size_t conv_elems = (size_t)NB * COUT * TLEN;
    if ((size_t)out_size > conv_elems) {
        cudaMemcpyAsync(out + conv_elems, c_trg,
                        (out_size - conv_elems) * sizeof(float),
                        cudaMemcpyDeviceToDevice);
    }
}

// round 9
// speedup vs baseline: 4.5582x; 2.0777x over previous
#include <cuda_runtime.h>
#include <cuda_fp16.h>
#include <cstdint>

#define NB   16
#define CIN  256
#define COUT 256
#define KS   5
#define SPK  128
#define TLEN 8192

#define OTI  64      // o tile per block
#define TTI  256     // t tile per block
#define ICH  32      // i chunk
#define XR   40      // padded row pitch (80B -> 16B-aligned quarters)
#define XT   260     // xs rows (t range: tile + 4 pad)
#define NCH  8       // CIN / ICH

#define XS_ST (XT * XR)          // 10400 elems per stage
#define WS_ST (KS * OTI * XR)    // 12800 elems per stage
#define SMEM_BYTES ((2 * XS_ST + 2 * WS_ST) * 2)   // 92800

// scratch (no cudaMalloc allowed)
__device__ float g_s[NB * CIN];
__device__ float g_demod[NB * COUT];
__device__ float g_wsqT[CIN * COUT];                         // [i][o]
__device__ __half g_wm[(size_t)NB * KS * COUT * CIN];        // [b][k][o][i]

// ---------------------------------------------------------------------------
__global__ void style_kernel(const float* __restrict__ c_trg,
                             const float* __restrict__ style_w,
                             const float* __restrict__ style_b) {
    int b = blockIdx.x;
    int i = threadIdx.x;
    const float* c = c_trg + b * SPK;
    const float* w = style_w + i * SPK;
    float acc = 0.f;
#pragma unroll 8
    for (int j = 0; j < SPK; ++j) acc += c[j] * w[j];
    g_s[b * CIN + i] = acc + style_b[i];
}

__global__ void wsq_kernel(const float* __restrict__ weight) {
    int i = blockIdx.x;
    int o = threadIdx.x;
    const float* wp = weight + ((size_t)o * CIN + i) * KS;
    float acc = 0.f;
#pragma unroll
    for (int k = 0; k < KS; ++k) acc += wp[k] * wp[k];
    g_wsqT[i * COUT + o] = acc;
}

__global__ void demod_kernel() {
    int b = blockIdx.x;
    int o = threadIdx.x;
    const float* sp = g_s + b * CIN;
    float acc = 0.f;
#pragma unroll 4
    for (int i = 0; i < CIN; ++i) {
        float s = sp[i];
        acc += s * s * g_wsqT[i * COUT + o];
    }
    g_demod[b * COUT + o] = rsqrtf(acc + 1e-8f);
}

// g_wm[b][k][o][i] = fp16( weight[o,i,k]*s[b,i]*demod[b,o] )
__global__ void wm_kernel(const float* __restrict__ weight) {
    int idx = blockIdx.x * blockDim.x + threadIdx.x;   // NB*KS*COUT*CIN
    int i = idx & (CIN - 1);
    int o = (idx >> 8) & (COUT - 1);
    int kb = idx >> 16;
    int k = kb % KS;
    int b = kb / KS;
    float wv = weight[((size_t)o * CIN + i) * KS + k]
             * g_s[b * CIN + i] * g_demod[b * COUT + o];
    g_wm[idx] = __float2half_rn(wv);
}

// ---------------------------------------------------------------------------
__device__ __forceinline__ void mma16816(float* d, const unsigned* a,
                                         unsigned b0, unsigned b1) {
    asm volatile(
        "mma.sync.aligned.m16n8k16.row.col.f32.f16.f16.f32 "
        "{%0,%1,%2,%3}, {%4,%5,%6,%7}, {%8,%9}, {%0,%1,%2,%3};"
        : "+f"(d[0]), "+f"(d[1]), "+f"(d[2]), "+f"(d[3])
        : "r"(a[0]), "r"(a[1]), "r"(a[2]), "r"(a[3]), "r"(b0), "r"(b1));
}
__device__ __forceinline__ unsigned lds32(const __half* p) {
    return *(const unsigned*)p;
}
__device__ __forceinline__ uint32_t smem_u32(const void* p) {
    uint32_t a;
    asm("{ .reg .u64 t; cvta.to.shared.u64 t, %1; cvt.u32.u64 %0, t; }"
        : "=r"(a) : "l"(p));
    return a;
}
__device__ __forceinline__ void cp16(uint32_t dst, const void* src) {
    asm volatile("cp.async.cg.shared.global [%0], [%1], 16;"
                 :: "r"(dst), "l"(src));
}
#define CP_COMMIT() asm volatile("cp.async.commit_group;" ::: "memory")
#define CP_WAIT0()  asm volatile("cp.async.wait_group 0;" ::: "memory")

__device__ __forceinline__ float ldg_f32(const float* p) {
    float v;
    asm volatile("ld.global.nc.f32 %0, [%1];" : "=f"(v) : "l"(p));
    return v;
}

// ---------------------------------------------------------------------------
// Main conv: out[b,o,t] = leaky( sum_{i,k} Wm[b,o,i,k] * x_reflpad[b,i,t+k] )
// fp16 mma.sync single-term, double-buffered smem + cp.async weights.
__global__ __launch_bounds__(256, 1)
void conv_kernel(const float* __restrict__ x, float* __restrict__ out) {
    extern __shared__ __align__(16) __half sm[];
    __half* xs = sm;                        // [2][XS_ST]
    __half* ws = sm + 2 * XS_ST;            // [2][WS_ST]
    const uint32_t ws_a = smem_u32(ws);

    const int b  = blockIdx.z;
    const int ob = blockIdx.y * OTI;
    const int tb = blockIdx.x * TTI;
    const int tid = threadIdx.x;
    const int wid = tid >> 5;
    const int lane = tid & 31;
    const int wo = wid & 1;           // o warp (2): 32 o each
    const int wt = wid >> 1;          // t warp (4): 64 t each
    const int lq = lane >> 2;
    const int lr = lane & 3;

    float acc[2][8][4];
#pragma unroll
    for (int mt = 0; mt < 2; ++mt)
#pragma unroll
        for (int nt = 0; nt < 8; ++nt)
#pragma unroll
            for (int e = 0; e < 4; ++e) acc[mt][nt][e] = 0.f;

    const float* xb = x + (size_t)b * CIN * TLEN;
    const __half* wmb = g_wm + (size_t)b * KS * COUT * CIN;

    float xr[33];

    // ---- prefetch Ws for chunk at ic into stage st (pure cp.async, 16B chunks) ----
    // 320 rows x 64B data (80B pitch), 4 aligned 16B chunks each = 1280 cp16.
    auto prefetch_w = [&](int ic, int st) {
#pragma unroll
        for (int m = 0; m < 5; ++m) {
            int v = tid + 256 * m;                  // < 1280
            int row = v >> 2;                        // k*OTI + o  (0..319)
            int c4  = v & 3;                         // 16B chunk within row
            int k = row >> 6;
            int o = row & 63;
            const __half* src =
                wmb + ((size_t)(k * COUT + ob + o) * CIN + ic) + c4 * 8;
            uint32_t dst = ws_a + (uint32_t)(st * WS_ST + row * XR) * 2 + c4 * 16;
            cp16(dst, src);
        }
        CP_COMMIT();
    };
    // ---- issue x LDGs for chunk into regs (latency hidden under MMAs) ----
    auto load_x = [&](int ic) {
#pragma unroll
        for (int j = 0; j < 33; ++j) {
            int u = tid + 256 * j;
            if (u < ICH * XT) {
                int i  = u / XT;
                int tl = u - i * XT;
                int t  = tb + tl - 2;
                t = (t < 0) ? -t : ((t >= TLEN) ? (2 * TLEN - 2 - t) : t);
                xr[j] = ldg_f32(xb + (size_t)(ic + i) * TLEN + t);
            }
        }
    };
    // ---- convert + store x regs into stage st ----
    auto store_x = [&](int st) {
#pragma unroll
        for (int j = 0; j < 33; ++j) {
            int u = tid + 256 * j;
            if (u < ICH * XT) {
                int i  = u / XT;
                int tl = u - i * XT;
                xs[st * XS_ST + tl * XR + i] = __float2half_rn(xr[j]);
            }
        }
    };

    // ---- prologue: fill stage 0 ----
    prefetch_w(0, 0);
    load_x(0);
    store_x(0);
    CP_WAIT0();
    __syncthreads();

    for (int c = 0; c < NCH; ++c) {
        const int st = c & 1;
        const int nst = st ^ 1;
        if (c + 1 < NCH) {
            prefetch_w((c + 1) * ICH, nst);
            load_x((c + 1) * ICH);
        }

        // ---- MMA over stage st ----
        const __half* wsp = ws + st * WS_ST;
        const __half* xsp = xs + st * XS_ST;

        for (int tap = 0; tap < KS; ++tap) {
#pragma unroll
            for (int k16 = 0; k16 < ICH; k16 += 16) {
                unsigned ah[2][4];
#pragma unroll
                for (int mt = 0; mt < 2; ++mt) {
                    int row = tap * OTI + wo * 32 + mt * 16 + lq;
                    int col = k16 + lr * 2;
                    const __half* ph = wsp + row * XR + col;
                    ah[mt][0] = lds32(ph);
                    ah[mt][1] = lds32(ph + 8 * XR);
                    ah[mt][2] = lds32(ph + 8);
                    ah[mt][3] = lds32(ph + 8 * XR + 8);
                }
#pragma unroll
                for (int nt = 0; nt < 8; ++nt) {
                    int trow = wt * 64 + nt * 8 + lq + tap;
                    int col  = k16 + lr * 2;
                    const __half* ph = xsp + trow * XR + col;
                    unsigned bh0 = lds32(ph), bh1 = lds32(ph + 8);
#pragma unroll
                    for (int mt = 0; mt < 2; ++mt)
                        mma16816(acc[mt][nt], ah[mt], bh0, bh1);
                }
            }
        }

        if (c + 1 < NCH) {
            store_x(nst);
            CP_WAIT0();
        }
        __syncthreads();
    }

    // ---- epilogue: leaky relu + store ----
#pragma unroll
    for (int mt = 0; mt < 2; ++mt) {
#pragma unroll
        for (int nt = 0; nt < 8; ++nt) {
            int o0 = ob + wo * 32 + mt * 16 + lq;
            int t0 = tb + wt * 64 + nt * 8 + lr * 2;
            float z0 = acc[mt][nt][0], z1 = acc[mt][nt][1];
            float z2 = acc[mt][nt][2], z3 = acc[mt][nt][3];
            z0 = (z0 > 0.f) ? z0 : 0.2f * z0;
            z1 = (z1 > 0.f) ? z1 : 0.2f * z1;
            z2 = (z2 > 0.f) ? z2 : 0.2f * z2;
            z3 = (z3 > 0.f) ? z3 : 0.2f * z3;
            float* p0 = out + ((size_t)b * COUT + o0) * TLEN + t0;
            *(float2*)p0 = make_float2(z0, z1);
            *(float2*)(p0 + 8 * TLEN) = make_float2(z2, z3);
        }
    }
}

// ---------------------------------------------------------------------------
extern "C" void kernel_launch(void* const* d_in, const int* in_sizes, int n_in,
                              void* d_out, int out_size) {
    const float* x       = (const float*)d_in[0];   // [16,256,8192]
    const float* c_trg   = (const float*)d_in[1];   // [16,128]
    const float* style_w = (const float*)d_in[2];   // [256,128]
    const float* style_b = (const float*)d_in[3];   // [256]
    const float* weight  = (const float*)d_in[4];   // [1,256,256,5]
    float* out = (float*)d_out;

    style_kernel<<<NB, CIN>>>(c_trg, style_w, style_b);
    wsq_kernel<<<CIN, COUT>>>(weight);
    demod_kernel<<<NB, COUT>>>();
    wm_kernel<<<(NB * KS * CIN * COUT) / 256, 256>>>(weight);

    static bool attr_done = false;
    if (!attr_done) {
        cudaFuncSetAttribute(conv_kernel,
                             cudaFuncAttributeMaxDynamicSharedMemorySize,
                             SMEM_BYTES);
        attr_done = true;
    }
    dim3 grid(TLEN / TTI, COUT / OTI, NB);        // (32, 4, 16)
    conv_kernel<<<grid, 256, SMEM_BYTES>>>(x, out);

    size_t conv_elems = (size_t)NB * COUT * TLEN;
    if ((size_t)out_size > conv_elems) {
        cudaMemcpyAsync(out + conv_elems, c_trg,
                        (out_size - conv_elems) * sizeof(float),
                        cudaMemcpyDeviceToDevice);
    }
}